// round 15
// baseline (speedup 1.0000x reference)
#include <cuda_runtime.h>
#include <cuda_bf16.h>
#include <math.h>
#include <stdint.h>

#define HWDIM 128
#define NPIX 16384
#define CIN 256
#define COUT 256
#define KK 2304
#define NANCH 147456
#define TOPN 6000
#define NW 94
#define POSTN 1000
#define EQCAP 4096

typedef unsigned long long ull;

// ---------------- device scratch ----------------
__device__ float g_wT[KK * COUT];        // [k][n], k = (ky*3+kx)*256 + ci  (NHWC patch order)
__device__ float g_wh[CIN * 54];         // head weights [ci][o]
__device__ float g_x[COUT * NPIX];       // relu(conv3x3) [n][pix]
__device__ float g_scores[NANCH];
__device__ float g_boxes[NANCH * 4];
__device__ unsigned g_hist1[65536];
__device__ unsigned g_hist2[65536];
__device__ int g_cnt1, g_cnteq;
__device__ int g_T, g_Cabove, g_C1, g_R2;
__device__ unsigned g_Kstar;
__device__ int g_eq[EQCAP];
__device__ ull g_keys[8192];
__device__ float g_selbox[TOPN * 4];
__device__ ull g_mask[(size_t)TOPN * NW];

__device__ __forceinline__ unsigned smem_u32(const void* p) {
    return (unsigned)__cvta_generic_to_shared(p);
}
#define CP_ASYNC16(dst, src) \
    asm volatile("cp.async.ca.shared.global [%0], [%1], 16;" :: "r"(dst), "l"(src))
#define CP_COMMIT() asm volatile("cp.async.commit_group;" ::: "memory")
#define CP_WAIT0()  asm volatile("cp.async.wait_group 0;" ::: "memory")

// ---------------- zero ----------------
__global__ void zero_kernel(float* out) {
    int i = blockIdx.x * blockDim.x + threadIdx.x;
    if (i < 65536) { g_hist1[i] = 0u; g_hist2[i] = 0u; }
    if (i < 5000) out[i] = 0.f;
    if (i == 0) { g_cnt1 = 0; g_cnteq = 0; }
}

// ---------------- weight transposes ----------------
// rpn_w[n][ci][ky][kx] (OIHW) -> g_wT[(r*256+ci)*256 + n], r = ky*3+kx
__global__ void wtrans_kernel(const float* __restrict__ w) {
    int idx = blockIdx.x * blockDim.x + threadIdx.x;
    if (idx >= KK * COUT) return;
    int n = idx & 255;
    int k = idx >> 8;        // k = r*256 + ci
    int ci = k & 255;
    int r = k >> 8;
    g_wT[idx] = w[n * KK + ci * 9 + r];
}

__global__ void htrans_kernel(const float* __restrict__ cls_w, const float* __restrict__ box_w) {
    int idx = blockIdx.x * blockDim.x + threadIdx.x;
    if (idx >= CIN * 54) return;
    int ci = idx / 54;
    int o = idx - ci * 54;
    g_wh[idx] = (o < 18) ? cls_w[o * CIN + ci] : box_w[(o - 18) * CIN + ci];
}

// ---------------- conv 3x3 SAME + bias + relu (implicit GEMM, f32x2 FMA) ------
// K order: (ky, kx, ci-fastest) — sequential accumulation per output scalar.
// Best-measured config (579us) + hoisted per-kt address math (identical loads):
// all 8 k's of a kt share tap r = kt>>5, so border/offset compute once per kt.
__global__ void __launch_bounds__(128)
conv3x3_kernel(const float* __restrict__ feat, const float* __restrict__ bias) {
    __shared__ float Fs[2][8][128];
    __shared__ ull   Ws2[2][8][64];    // (w,w) packed pairs
    const int tid = threadIdx.x;
    const int tx = tid & 15;
    const int ty = tid >> 4;
    const int y  = blockIdx.x;
    const int n0 = blockIdx.y * 64;
    const int wn = tid & 63;
    const int wk = tid >> 6;

    ull acc2[8][4];
#pragma unroll
    for (int i = 0; i < 8; i++)
#pragma unroll
        for (int j = 0; j < 4; j++) acc2[i][j] = 0ull;

    float fv[8], wv[4];

#define CONV_LOAD(KT) do {                                                     \
    int r_  = (KT) >> 5;               /* tap 0..8, fixed for all 8 k's */     \
    int dy_ = r_ / 3;                                                          \
    int dx_ = r_ - dy_ * 3;                                                    \
    int yy_ = y + dy_ - 1;                                                     \
    int xx_ = tid + dx_ - 1;                                                   \
    bool ok_ = (yy_ >= 0) && (yy_ < 128) && (xx_ >= 0) && (xx_ < 128);         \
    const float* fp_ = feat + (((KT) & 31) * 8) * NPIX + yy_ * 128 + xx_;      \
    _Pragma("unroll")                                                          \
    for (int k_ = 0; k_ < 8; k_++)                                             \
        fv[k_] = ok_ ? fp_[k_ * NPIX] : 0.f;                                   \
    int k0_ = (KT) * 8;                                                        \
    _Pragma("unroll")                                                          \
    for (int u_ = 0; u_ < 4; u_++) {                                           \
        int kg_ = k0_ + wk + 2 * u_;                                           \
        wv[u_] = g_wT[kg_ * COUT + n0 + wn];                                   \
    } } while (0)

#define CONV_STORE(B) do {                                                     \
    _Pragma("unroll")                                                          \
    for (int k_ = 0; k_ < 8; k_++) Fs[(B)][k_][tid] = fv[k_];                  \
    _Pragma("unroll")                                                          \
    for (int u_ = 0; u_ < 4; u_++) {                                           \
        unsigned b_ = __float_as_uint(wv[u_]);                                 \
        Ws2[(B)][wk + 2 * u_][wn] = (ull)b_ | ((ull)b_ << 32);                 \
    } } while (0)

    CONV_LOAD(0);
    CONV_STORE(0);
    __syncthreads();

    int buf = 0;
    for (int kt = 0; kt < 288; kt++) {
        if (kt + 1 < 288) CONV_LOAD(kt + 1);
#pragma unroll
        for (int kk = 0; kk < 8; kk++) {
            ulonglong2 av0 = *(const ulonglong2*)&Fs[buf][kk][tx * 8];
            ulonglong2 av1 = *(const ulonglong2*)&Fs[buf][kk][tx * 8 + 4];
            const ulonglong2* wp2 = (const ulonglong2*)&Ws2[buf][kk][ty * 8];
            ulonglong2 wv0 = wp2[0], wv1 = wp2[1], wv2 = wp2[2], wv3 = wp2[3];
            ull A[4] = {av0.x, av0.y, av1.x, av1.y};
            ull W[8] = {wv0.x, wv0.y, wv1.x, wv1.y, wv2.x, wv2.y, wv3.x, wv3.y};
#pragma unroll
            for (int i = 0; i < 8; i++)
#pragma unroll
                for (int j = 0; j < 4; j++)
                    asm("fma.rn.f32x2 %0, %1, %2, %0;"
                        : "+l"(acc2[i][j]) : "l"(W[i]), "l"(A[j]));
        }
        if (kt + 1 < 288) {
            CONV_STORE(buf ^ 1);
            __syncthreads();
            buf ^= 1;
        }
    }

    const int px = y * 128 + tx * 8;
#pragma unroll
    for (int i = 0; i < 8; i++) {
        int n = n0 + ty * 8 + i;
        float b = bias[n];
        float o[8];
#pragma unroll
        for (int j = 0; j < 4; j++) {
            unsigned lo, hi;
            asm("mov.b64 {%0, %1}, %2;" : "=r"(lo), "=r"(hi) : "l"(acc2[i][j]));
            o[2 * j]     = fmaxf(__fadd_rn(__uint_as_float(lo), b), 0.f);
            o[2 * j + 1] = fmaxf(__fadd_rn(__uint_as_float(hi), b), 0.f);
        }
        float4 v0 = make_float4(o[0], o[1], o[2], o[3]);
        float4 v1 = make_float4(o[4], o[5], o[6], o[7]);
        *(float4*)&g_x[n * NPIX + px]     = v0;
        *(float4*)&g_x[n * NPIX + px + 4] = v1;
    }
}

// ---------------- heads + softmax + decode (fp32, XLA-op-faithful) ------------
__global__ void __launch_bounds__(128)
head_kernel(const float* __restrict__ cls_b, const float* __restrict__ box_b,
            const int* __restrict__ p_imh, const int* __restrict__ p_imw) {
    __shared__ float ws[64 * 54];
    const int tid = threadIdx.x;
    const int p = blockIdx.x * 128 + tid;

    float acc[54];
#pragma unroll
    for (int o = 0; o < 54; o++) acc[o] = 0.f;

    for (int c = 0; c < 4; c++) {
        for (int u = tid; u < 64 * 54; u += 128) ws[u] = g_wh[c * 64 * 54 + u];
        __syncthreads();
        for (int ci = 0; ci < 64; ci++) {
            float v = g_x[(c * 64 + ci) * NPIX + p];
            const float* wr = &ws[ci * 54];
#pragma unroll
            for (int o = 0; o < 54; o++) acc[o] = fmaf(v, wr[o], acc[o]);
        }
        __syncthreads();
    }

    float logit[18];
    float mx = -1e30f;
#pragma unroll
    for (int o = 0; o < 18; o++) { logit[o] = __fadd_rn(acc[o], cls_b[o]); mx = fmaxf(mx, logit[o]); }
    float ex[18], se = 0.f;
#pragma unroll
    for (int o = 0; o < 18; o++) { ex[o] = expf(__fsub_rn(logit[o], mx)); se = __fadd_rn(se, ex[o]); }

    const int xcoord = p & 127;
    const int ycoord = p >> 7;
    const float imw1 = (float)(*p_imw) - 1.f;
    const float imh1 = (float)(*p_imh) - 1.f;
    const float cxa = xcoord * 32.f + 7.5f;
    const float cya = ycoord * 32.f + 7.5f;
    const float ws_t[3] = {23.f, 16.f, 11.f};
    const float hs_t[3] = {12.f, 16.f, 22.f};
    const float NEG_INF = __int_as_float(0xff800000);

#pragma unroll
    for (int a = 0; a < 9; a++) {
        int ri = a / 3, si = a - ri * 3;
        float scale = (float)(16 << si);
        float wa = ws_t[ri] * scale;
        float ha = hs_t[ri] * scale;
        float d0 = __fadd_rn(acc[18 + 4 * a + 0], box_b[4 * a + 0]);
        float d1 = __fadd_rn(acc[18 + 4 * a + 1], box_b[4 * a + 1]);
        float d2 = __fadd_rn(acc[18 + 4 * a + 2], box_b[4 * a + 2]);
        float d3 = __fadd_rn(acc[18 + 4 * a + 3], box_b[4 * a + 3]);
        float cx = __fadd_rn(__fmul_rn(d0, wa), cxa);
        float cy = __fadd_rn(__fmul_rn(d1, ha), cya);
        float pw = __fmul_rn(wa, expf(d2));
        float ph = __fmul_rn(ha, expf(d3));
        float hpw = __fmul_rn(0.5f, pw);
        float hph = __fmul_rn(0.5f, ph);
        float x1 = fminf(fmaxf(__fsub_rn(cx, hpw), 0.f), imw1);
        float y1 = fminf(fmaxf(__fsub_rn(cy, hph), 0.f), imh1);
        float x2 = fminf(fmaxf(__fadd_rn(cx, hpw), 0.f), imw1);
        float y2 = fminf(fmaxf(__fadd_rn(cy, hph), 0.f), imh1);
        bool valid = (__fadd_rn(__fsub_rn(x2, x1), 1.f) >= 16.f) &&
                     (__fadd_rn(__fsub_rn(y2, y1), 1.f) >= 16.f);
        float sc = valid ? __fdiv_rn(ex[9 + a], se) : NEG_INF;
        int n = p * 9 + a;
        g_scores[n] = sc;
        g_boxes[n * 4 + 0] = x1;
        g_boxes[n * 4 + 1] = y1;
        g_boxes[n * 4 + 2] = x2;
        g_boxes[n * 4 + 3] = y2;
    }
}

// ---------------- top-k ----------------
__device__ __forceinline__ unsigned flip_key(float s) {
    unsigned u = __float_as_uint(s);
    return (u & 0x80000000u) ? ~u : (u | 0x80000000u);
}

__global__ void hist1_kernel() {
    int i = blockIdx.x * blockDim.x + threadIdx.x;
    if (i < NANCH) atomicAdd(&g_hist1[flip_key(g_scores[i]) >> 16], 1u);
}

__global__ void findT_kernel() {
    __shared__ unsigned part[1024];
    int t = threadIdx.x;
    unsigned s = 0;
    for (int b = 0; b < 64; b++) s += g_hist1[t * 64 + b];
    part[t] = s;
    __syncthreads();
    if (t == 0) {
        unsigned acc = 0;
        int seg = 0;
        for (int i = 1023; i >= 0; i--) {
            if (acc + part[i] >= (unsigned)TOPN) { seg = i; break; }
            acc += part[i];
        }
        int T = seg * 64;
        unsigned cab = acc;
        for (int b = seg * 64 + 63; b >= seg * 64; b--) {
            unsigned h = g_hist1[b];
            if (cab + h >= (unsigned)TOPN) { T = b; break; }
            cab += h;
        }
        g_T = T;
        g_Cabove = (int)cab;
    }
}

__global__ void hist2_kernel() {
    int i = blockIdx.x * blockDim.x + threadIdx.x;
    if (i < NANCH) {
        unsigned k = flip_key(g_scores[i]);
        if ((int)(k >> 16) == g_T) atomicAdd(&g_hist2[k & 0xFFFFu], 1u);
    }
}

__global__ void findL_kernel() {
    __shared__ unsigned part[1024];
    int t = threadIdx.x;
    unsigned s = 0;
    for (int b = 0; b < 64; b++) s += g_hist2[t * 64 + b];
    part[t] = s;
    __syncthreads();
    if (t == 0) {
        unsigned R = (unsigned)(TOPN - g_Cabove);
        unsigned acc = 0;
        int seg = 0;
        for (int i = 1023; i >= 0; i--) {
            if (acc + part[i] >= R) { seg = i; break; }
            acc += part[i];
        }
        int L = seg * 64;
        unsigned cab = acc;
        for (int b = seg * 64 + 63; b >= seg * 64; b--) {
            unsigned h = g_hist2[b];
            if (cab + h >= R) { L = b; break; }
            cab += h;
        }
        int C1 = g_Cabove + (int)cab;
        g_C1 = C1;
        g_R2 = TOPN - C1;
        g_Kstar = (((unsigned)g_T) << 16) | (unsigned)L;
    }
}

__global__ void compact_kernel() {
    int i = blockIdx.x * blockDim.x + threadIdx.x;
    if (i >= NANCH) return;
    unsigned k = flip_key(g_scores[i]);
    unsigned Ks = g_Kstar;
    if (k > Ks) {
        int p = atomicAdd(&g_cnt1, 1);
        g_keys[p] = (((ull)(~k)) << 32) | (unsigned)i;
    } else if (k == Ks) {
        int p = atomicAdd(&g_cnteq, 1);
        if (p < EQCAP) g_eq[p] = i;
    }
}

// Select the R2 smallest eq indices (rank-select; same result as sort+take-R2)
// and append to g_keys[C1..TOPN).
__global__ void eqsel_kernel() {
    __shared__ int e[EQCAP];
    int t = threadIdx.x;
    int n = g_cnteq;
    if (n > EQCAP) n = EQCAP;
    int C1 = g_C1, R2 = g_R2;
    unsigned nk = ~g_Kstar;
    for (int i = t; i < n; i += 1024) e[i] = g_eq[i];
    __syncthreads();
    for (int i = t; i < n; i += 1024) {
        int ei = e[i];
        int r = 0;
        for (int j = 0; j < n; j++) r += (e[j] < ei);
        if (r < R2) g_keys[C1 + r] = (((ull)nk) << 32) | (unsigned)ei;
    }
}

// Rank-scatter: unique 64-bit keys; rank_i = #{j: key_j < key_i} reproduces the
// ascending sort order exactly (score desc, idx asc). 47 blocks x 128 threads.
__global__ void __launch_bounds__(128)
rank_kernel() {
    __shared__ ull sk[TOPN];
    const int t = threadIdx.x;
    for (int i = t; i < TOPN; i += 128) sk[i] = g_keys[i];
    __syncthreads();
    const int i = blockIdx.x * 128 + t;
    if (i >= TOPN) return;
    const ull ki = sk[i];
    int rank = 0;
#pragma unroll 4
    for (int j = 0; j < TOPN; j++) rank += (sk[j] < ki) ? 1 : 0;
    unsigned idx = (unsigned)ki;
    float4 b = *(const float4*)&g_boxes[(size_t)idx * 4];
    *(float4*)&g_selbox[rank * 4] = b;
}

// ---------------- NMS ----------------
// Upper triangle only. Divide-free exact IoU threshold:
// fl(inter/uni) > 0.7f  <=>  inter >= MID*uni in exact (double) arithmetic,
// MID = midpoint(0.7f, nextafterf(0.7f)) — the RN tie rounds up (even mantissa).
__global__ void mask_kernel() {
    __shared__ float4 cb[64];
    __shared__ float ca[64];
    int jb = blockIdx.x, ib = blockIdx.y;
    if (jb < ib) return;
    int t = threadIdx.x;
    int j0 = jb * 64;
    int nj = TOPN - j0;
    if (nj > 64) nj = 64;
    if (t < nj) {
        float4 q = *(const float4*)&g_selbox[(j0 + t) * 4];
        cb[t] = q;
        ca[t] = __fmul_rn(__fadd_rn(__fsub_rn(q.z, q.x), 1.f),
                          __fadd_rn(__fsub_rn(q.w, q.y), 1.f));
    }
    __syncthreads();
    int i = ib * 64 + t;
    if (i >= TOPN) return;
    float4 rb = *(const float4*)&g_selbox[i * 4];
    float ra = __fmul_rn(__fadd_rn(__fsub_rn(rb.z, rb.x), 1.f),
                         __fadd_rn(__fsub_rn(rb.w, rb.y), 1.f));
    const double MID = ((double)__uint_as_float(0x3F333333u) +
                        (double)__uint_as_float(0x3F333334u)) * 0.5;
    ull bits = 0;
    for (int c = 0; c < nj; c++) {
        float4 q = cb[c];
        float xx1 = fmaxf(rb.x, q.x), yy1 = fmaxf(rb.y, q.y);
        float xx2 = fminf(rb.z, q.z), yy2 = fminf(rb.w, q.w);
        float w = fmaxf(__fadd_rn(__fsub_rn(xx2, xx1), 1.f), 0.f);
        float h = fmaxf(__fadd_rn(__fsub_rn(yy2, yy1), 1.f), 0.f);
        float inter = __fmul_rn(w, h);
        float uni = __fsub_rn(__fadd_rn(ra, ca[c]), inter);
        if ((double)inter >= MID * (double)uni) bits |= (1ull << c);
    }
    g_mask[(size_t)i * NW + jb] = bits;
}

// Chunked, double-buffered serial resolution with ffs-skip over dead rows.
__global__ void nms_kernel(float* __restrict__ out) {
    extern __shared__ ull buf[];          // [2][64][NW]
    __shared__ ull rem[NW];
    __shared__ int kept;
    const int t = threadIdx.x;            // 128 threads
    if (t < NW) rem[t] = 0ull;
    if (t == 0) kept = 0;
    __syncthreads();

    const int NCHUNK = (TOPN + 63) / 64;  // 94

    auto load_chunk = [&](int c, int b) {
        int c0 = c & ~1;                  // 16B alignment (row stride 94*8 = 47*16)
        int pairs = (NW - c0) >> 1;
        int nrows = TOPN - c * 64; if (nrows > 64) nrows = 64;
        int tot = nrows * pairs;
        for (int u = t; u < tot; u += 128) {
            int il = u / pairs, pj = u - il * pairs;
            int w = c0 + pj * 2;
            const ull* src = &g_mask[(size_t)(c * 64 + il) * NW + w];
            unsigned dst = smem_u32(&buf[((size_t)b * 64 + il) * NW + w]);
            CP_ASYNC16(dst, src);
        }
        CP_COMMIT();
    };

    load_chunk(0, 0);
    CP_WAIT0();
    __syncthreads();

    bool done = false;
    for (int c = 0; c < NCHUNK && !done; c++) {
        int b = c & 1;
        if (c + 1 < NCHUNK) load_chunk(c + 1, b ^ 1);
        int nrows = TOPN - c * 64; if (nrows > 64) nrows = 64;
        ull rowmask = (nrows == 64) ? ~0ull : ((1ull << nrows) - 1ull);
        int il = 0;
        while (il < 64) {
            ull w = ~rem[c] & rowmask & (~0ull << il);
            if (!w) break;
            il = __ffsll(w) - 1;
            int i = c * 64 + il;
            if (t >= c && t < NW) rem[t] |= buf[((size_t)b * 64 + il) * NW + t];
            if (t == 0) {
                float4 bx = *(const float4*)&g_selbox[i * 4];
                int r = kept;
                out[r * 5 + 0] = 0.f;
                out[r * 5 + 1] = bx.x;
                out[r * 5 + 2] = bx.y;
                out[r * 5 + 3] = bx.z;
                out[r * 5 + 4] = bx.w;
                kept = r + 1;
            }
            __syncthreads();
            if (kept >= POSTN) { done = true; break; }
            il++;
        }
        CP_WAIT0();
        __syncthreads();
    }
}

// ---------------- launch ----------------
extern "C" void kernel_launch(void* const* d_in, const int* in_sizes, int n_in,
                              void* d_out, int out_size) {
    const float* features = (const float*)d_in[0];
    const float* rpn_w = (const float*)d_in[1];
    const float* rpn_b = (const float*)d_in[2];
    const float* cls_w = (const float*)d_in[3];
    const float* cls_b = (const float*)d_in[4];
    const float* box_w = (const float*)d_in[5];
    const float* box_b = (const float*)d_in[6];
    const int* imh = (const int*)d_in[7];
    const int* imw = (const int*)d_in[8];
    float* out = (float*)d_out;

    const int NMS_SMEM = 2 * 64 * NW * sizeof(ull);   // 96 KB

    static int smem_set = 0;
    if (!smem_set) {
        cudaFuncSetAttribute(nms_kernel, cudaFuncAttributeMaxDynamicSharedMemorySize, NMS_SMEM);
        smem_set = 1;
    }

    zero_kernel<<<256, 256>>>(out);
    wtrans_kernel<<<(KK * COUT + 255) / 256, 256>>>(rpn_w);
    htrans_kernel<<<54, 256>>>(cls_w, box_w);
    conv3x3_kernel<<<dim3(128, 4), 128>>>(features, rpn_b);
    head_kernel<<<128, 128>>>(cls_b, box_b, imh, imw);
    hist1_kernel<<<576, 256>>>();
    findT_kernel<<<1, 1024>>>();
    hist2_kernel<<<576, 256>>>();
    findL_kernel<<<1, 1024>>>();
    compact_kernel<<<576, 256>>>();
    eqsel_kernel<<<1, 1024>>>();
    rank_kernel<<<47, 128>>>();
    mask_kernel<<<dim3(NW, NW), 64>>>();
    nms_kernel<<<1, 128, NMS_SMEM>>>(out);
}

// round 16
// speedup vs baseline: 1.1143x; 1.1143x over previous
#include <cuda_runtime.h>
#include <cuda_bf16.h>
#include <math.h>
#include <stdint.h>

#define HWDIM 128
#define NPIX 16384
#define CIN 256
#define COUT 256
#define KK 2304
#define NANCH 147456
#define TOPN 6000
#define NW 94
#define POSTN 1000
#define EQCAP 4096

typedef unsigned long long ull;

// ---------------- device scratch ----------------
__device__ float g_wT[KK * COUT];        // [k][n], k = (ky*3+kx)*256 + ci  (NHWC patch order)
__device__ float g_wh[CIN * 54];         // head weights [ci][o]
__device__ float g_x[COUT * NPIX];       // relu(conv3x3) [n][pix]
__device__ float g_scores[NANCH];
__device__ float g_boxes[NANCH * 4];
__device__ unsigned g_hist1[65536];
__device__ unsigned g_hist2[65536];
__device__ int g_cnt1, g_cnteq;
__device__ int g_T, g_Cabove, g_C1, g_R2;
__device__ unsigned g_Kstar;
__device__ int g_eq[EQCAP];
__device__ ull g_keys[8192];
__device__ float g_selbox[TOPN * 4];
__device__ ull g_mask[(size_t)TOPN * NW];

__device__ __forceinline__ unsigned smem_u32(const void* p) {
    return (unsigned)__cvta_generic_to_shared(p);
}
#define CP_ASYNC16(dst, src) \
    asm volatile("cp.async.ca.shared.global [%0], [%1], 16;" :: "r"(dst), "l"(src))
#define CP_COMMIT() asm volatile("cp.async.commit_group;" ::: "memory")
#define CP_WAIT0()  asm volatile("cp.async.wait_group 0;" ::: "memory")

// ---------------- zero ----------------
__global__ void zero_kernel(float* out) {
    int i = blockIdx.x * blockDim.x + threadIdx.x;
    if (i < 65536) { g_hist1[i] = 0u; g_hist2[i] = 0u; }
    if (i < 5000) out[i] = 0.f;
    if (i == 0) { g_cnt1 = 0; g_cnteq = 0; }
}

// ---------------- weight transposes ----------------
__global__ void wtrans_kernel(const float* __restrict__ w) {
    int idx = blockIdx.x * blockDim.x + threadIdx.x;
    if (idx >= KK * COUT) return;
    int n = idx & 255;
    int k = idx >> 8;        // k = r*256 + ci
    int ci = k & 255;
    int r = k >> 8;
    g_wT[idx] = w[n * KK + ci * 9 + r];
}

__global__ void htrans_kernel(const float* __restrict__ cls_w, const float* __restrict__ box_w) {
    int idx = blockIdx.x * blockDim.x + threadIdx.x;
    if (idx >= CIN * 54) return;
    int ci = idx / 54;
    int o = idx - ci * 54;
    g_wh[idx] = (o < 18) ? cls_w[o * CIN + ci] : box_w[(o - 18) * CIN + ci];
}

// ---------------- conv 3x3 SAME + bias + relu (implicit GEMM, f32x2 FMA) ------
// K order: (ky, kx, ci-fastest) — sequential accumulation per output scalar.
// Best config (565us): hoisted per-kt tap/border math, identical loads.
__global__ void __launch_bounds__(128)
conv3x3_kernel(const float* __restrict__ feat, const float* __restrict__ bias) {
    __shared__ float Fs[2][8][128];
    __shared__ ull   Ws2[2][8][64];    // (w,w) packed pairs
    const int tid = threadIdx.x;
    const int tx = tid & 15;
    const int ty = tid >> 4;
    const int y  = blockIdx.x;
    const int n0 = blockIdx.y * 64;
    const int wn = tid & 63;
    const int wk = tid >> 6;

    ull acc2[8][4];
#pragma unroll
    for (int i = 0; i < 8; i++)
#pragma unroll
        for (int j = 0; j < 4; j++) acc2[i][j] = 0ull;

    float fv[8], wv[4];

#define CONV_LOAD(KT) do {                                                     \
    int r_  = (KT) >> 5;               /* tap 0..8, fixed for all 8 k's */     \
    int dy_ = r_ / 3;                                                          \
    int dx_ = r_ - dy_ * 3;                                                    \
    int yy_ = y + dy_ - 1;                                                     \
    int xx_ = tid + dx_ - 1;                                                   \
    bool ok_ = (yy_ >= 0) && (yy_ < 128) && (xx_ >= 0) && (xx_ < 128);         \
    const float* fp_ = feat + (((KT) & 31) * 8) * NPIX + yy_ * 128 + xx_;      \
    _Pragma("unroll")                                                          \
    for (int k_ = 0; k_ < 8; k_++)                                             \
        fv[k_] = ok_ ? fp_[k_ * NPIX] : 0.f;                                   \
    int k0_ = (KT) * 8;                                                        \
    _Pragma("unroll")                                                          \
    for (int u_ = 0; u_ < 4; u_++) {                                           \
        int kg_ = k0_ + wk + 2 * u_;                                           \
        wv[u_] = g_wT[kg_ * COUT + n0 + wn];                                   \
    } } while (0)

#define CONV_STORE(B) do {                                                     \
    _Pragma("unroll")                                                          \
    for (int k_ = 0; k_ < 8; k_++) Fs[(B)][k_][tid] = fv[k_];                  \
    _Pragma("unroll")                                                          \
    for (int u_ = 0; u_ < 4; u_++) {                                           \
        unsigned b_ = __float_as_uint(wv[u_]);                                 \
        Ws2[(B)][wk + 2 * u_][wn] = (ull)b_ | ((ull)b_ << 32);                 \
    } } while (0)

    CONV_LOAD(0);
    CONV_STORE(0);
    __syncthreads();

    int buf = 0;
    for (int kt = 0; kt < 288; kt++) {
        if (kt + 1 < 288) CONV_LOAD(kt + 1);
#pragma unroll
        for (int kk = 0; kk < 8; kk++) {
            ulonglong2 av0 = *(const ulonglong2*)&Fs[buf][kk][tx * 8];
            ulonglong2 av1 = *(const ulonglong2*)&Fs[buf][kk][tx * 8 + 4];
            const ulonglong2* wp2 = (const ulonglong2*)&Ws2[buf][kk][ty * 8];
            ulonglong2 wv0 = wp2[0], wv1 = wp2[1], wv2 = wp2[2], wv3 = wp2[3];
            ull A[4] = {av0.x, av0.y, av1.x, av1.y};
            ull W[8] = {wv0.x, wv0.y, wv1.x, wv1.y, wv2.x, wv2.y, wv3.x, wv3.y};
#pragma unroll
            for (int i = 0; i < 8; i++)
#pragma unroll
                for (int j = 0; j < 4; j++)
                    asm("fma.rn.f32x2 %0, %1, %2, %0;"
                        : "+l"(acc2[i][j]) : "l"(W[i]), "l"(A[j]));
        }
        if (kt + 1 < 288) {
            CONV_STORE(buf ^ 1);
            __syncthreads();
            buf ^= 1;
        }
    }

    const int px = y * 128 + tx * 8;
#pragma unroll
    for (int i = 0; i < 8; i++) {
        int n = n0 + ty * 8 + i;
        float b = bias[n];
        float o[8];
#pragma unroll
        for (int j = 0; j < 4; j++) {
            unsigned lo, hi;
            asm("mov.b64 {%0, %1}, %2;" : "=r"(lo), "=r"(hi) : "l"(acc2[i][j]));
            o[2 * j]     = fmaxf(__fadd_rn(__uint_as_float(lo), b), 0.f);
            o[2 * j + 1] = fmaxf(__fadd_rn(__uint_as_float(hi), b), 0.f);
        }
        float4 v0 = make_float4(o[0], o[1], o[2], o[3]);
        float4 v1 = make_float4(o[4], o[5], o[6], o[7]);
        *(float4*)&g_x[n * NPIX + px]     = v0;
        *(float4*)&g_x[n * NPIX + px + 4] = v1;
    }
}

// ---------------- heads + softmax + decode (fp32, XLA-op-faithful) ------------
__global__ void __launch_bounds__(128)
head_kernel(const float* __restrict__ cls_b, const float* __restrict__ box_b,
            const int* __restrict__ p_imh, const int* __restrict__ p_imw) {
    __shared__ float ws[64 * 54];
    const int tid = threadIdx.x;
    const int p = blockIdx.x * 128 + tid;

    float acc[54];
#pragma unroll
    for (int o = 0; o < 54; o++) acc[o] = 0.f;

    for (int c = 0; c < 4; c++) {
        for (int u = tid; u < 64 * 54; u += 128) ws[u] = g_wh[c * 64 * 54 + u];
        __syncthreads();
        for (int ci = 0; ci < 64; ci++) {
            float v = g_x[(c * 64 + ci) * NPIX + p];
            const float* wr = &ws[ci * 54];
#pragma unroll
            for (int o = 0; o < 54; o++) acc[o] = fmaf(v, wr[o], acc[o]);
        }
        __syncthreads();
    }

    float logit[18];
    float mx = -1e30f;
#pragma unroll
    for (int o = 0; o < 18; o++) { logit[o] = __fadd_rn(acc[o], cls_b[o]); mx = fmaxf(mx, logit[o]); }
    float ex[18], se = 0.f;
#pragma unroll
    for (int o = 0; o < 18; o++) { ex[o] = expf(__fsub_rn(logit[o], mx)); se = __fadd_rn(se, ex[o]); }

    const int xcoord = p & 127;
    const int ycoord = p >> 7;
    const float imw1 = (float)(*p_imw) - 1.f;
    const float imh1 = (float)(*p_imh) - 1.f;
    const float cxa = xcoord * 32.f + 7.5f;
    const float cya = ycoord * 32.f + 7.5f;
    const float ws_t[3] = {23.f, 16.f, 11.f};
    const float hs_t[3] = {12.f, 16.f, 22.f};
    const float NEG_INF = __int_as_float(0xff800000);

#pragma unroll
    for (int a = 0; a < 9; a++) {
        int ri = a / 3, si = a - ri * 3;
        float scale = (float)(16 << si);
        float wa = ws_t[ri] * scale;
        float ha = hs_t[ri] * scale;
        float d0 = __fadd_rn(acc[18 + 4 * a + 0], box_b[4 * a + 0]);
        float d1 = __fadd_rn(acc[18 + 4 * a + 1], box_b[4 * a + 1]);
        float d2 = __fadd_rn(acc[18 + 4 * a + 2], box_b[4 * a + 2]);
        float d3 = __fadd_rn(acc[18 + 4 * a + 3], box_b[4 * a + 3]);
        float cx = __fadd_rn(__fmul_rn(d0, wa), cxa);
        float cy = __fadd_rn(__fmul_rn(d1, ha), cya);
        float pw = __fmul_rn(wa, expf(d2));
        float ph = __fmul_rn(ha, expf(d3));
        float hpw = __fmul_rn(0.5f, pw);
        float hph = __fmul_rn(0.5f, ph);
        float x1 = fminf(fmaxf(__fsub_rn(cx, hpw), 0.f), imw1);
        float y1 = fminf(fmaxf(__fsub_rn(cy, hph), 0.f), imh1);
        float x2 = fminf(fmaxf(__fadd_rn(cx, hpw), 0.f), imw1);
        float y2 = fminf(fmaxf(__fadd_rn(cy, hph), 0.f), imh1);
        bool valid = (__fadd_rn(__fsub_rn(x2, x1), 1.f) >= 16.f) &&
                     (__fadd_rn(__fsub_rn(y2, y1), 1.f) >= 16.f);
        float sc = valid ? __fdiv_rn(ex[9 + a], se) : NEG_INF;
        int n = p * 9 + a;
        g_scores[n] = sc;
        g_boxes[n * 4 + 0] = x1;
        g_boxes[n * 4 + 1] = y1;
        g_boxes[n * 4 + 2] = x2;
        g_boxes[n * 4 + 3] = y2;
    }
}

// ---------------- top-k ----------------
__device__ __forceinline__ unsigned flip_key(float s) {
    unsigned u = __float_as_uint(s);
    return (u & 0x80000000u) ? ~u : (u | 0x80000000u);
}

__global__ void hist1_kernel() {
    int i = blockIdx.x * blockDim.x + threadIdx.x;
    if (i < NANCH) atomicAdd(&g_hist1[flip_key(g_scores[i]) >> 16], 1u);
}

__global__ void findT_kernel() {
    __shared__ unsigned part[1024];
    int t = threadIdx.x;
    unsigned s = 0;
    for (int b = 0; b < 64; b++) s += g_hist1[t * 64 + b];
    part[t] = s;
    __syncthreads();
    if (t == 0) {
        unsigned acc = 0;
        int seg = 0;
        for (int i = 1023; i >= 0; i--) {
            if (acc + part[i] >= (unsigned)TOPN) { seg = i; break; }
            acc += part[i];
        }
        int T = seg * 64;
        unsigned cab = acc;
        for (int b = seg * 64 + 63; b >= seg * 64; b--) {
            unsigned h = g_hist1[b];
            if (cab + h >= (unsigned)TOPN) { T = b; break; }
            cab += h;
        }
        g_T = T;
        g_Cabove = (int)cab;
    }
}

__global__ void hist2_kernel() {
    int i = blockIdx.x * blockDim.x + threadIdx.x;
    if (i < NANCH) {
        unsigned k = flip_key(g_scores[i]);
        if ((int)(k >> 16) == g_T) atomicAdd(&g_hist2[k & 0xFFFFu], 1u);
    }
}

__global__ void findL_kernel() {
    __shared__ unsigned part[1024];
    int t = threadIdx.x;
    unsigned s = 0;
    for (int b = 0; b < 64; b++) s += g_hist2[t * 64 + b];
    part[t] = s;
    __syncthreads();
    if (t == 0) {
        unsigned R = (unsigned)(TOPN - g_Cabove);
        unsigned acc = 0;
        int seg = 0;
        for (int i = 1023; i >= 0; i--) {
            if (acc + part[i] >= R) { seg = i; break; }
            acc += part[i];
        }
        int L = seg * 64;
        unsigned cab = acc;
        for (int b = seg * 64 + 63; b >= seg * 64; b--) {
            unsigned h = g_hist2[b];
            if (cab + h >= R) { L = b; break; }
            cab += h;
        }
        int C1 = g_Cabove + (int)cab;
        g_C1 = C1;
        g_R2 = TOPN - C1;
        g_Kstar = (((unsigned)g_T) << 16) | (unsigned)L;
    }
}

__global__ void compact_kernel() {
    int i = blockIdx.x * blockDim.x + threadIdx.x;
    if (i >= NANCH) return;
    unsigned k = flip_key(g_scores[i]);
    unsigned Ks = g_Kstar;
    if (k > Ks) {
        int p = atomicAdd(&g_cnt1, 1);
        g_keys[p] = (((ull)(~k)) << 32) | (unsigned)i;
    } else if (k == Ks) {
        int p = atomicAdd(&g_cnteq, 1);
        if (p < EQCAP) g_eq[p] = i;
    }
}

__global__ void eqsel_kernel() {
    __shared__ int e[EQCAP];
    int t = threadIdx.x;
    int n = g_cnteq;
    if (n > EQCAP) n = EQCAP;
    int C1 = g_C1, R2 = g_R2;
    unsigned nk = ~g_Kstar;
    for (int i = t; i < n; i += 1024) e[i] = g_eq[i];
    __syncthreads();
    for (int i = t; i < n; i += 1024) {
        int ei = e[i];
        int r = 0;
        for (int j = 0; j < n; j++) r += (e[j] < ei);
        if (r < R2) g_keys[C1 + r] = (((ull)nk) << 32) | (unsigned)ei;
    }
}

__global__ void __launch_bounds__(128)
rank_kernel() {
    __shared__ ull sk[TOPN];
    const int t = threadIdx.x;
    for (int i = t; i < TOPN; i += 128) sk[i] = g_keys[i];
    __syncthreads();
    const int i = blockIdx.x * 128 + t;
    if (i >= TOPN) return;
    const ull ki = sk[i];
    int rank = 0;
#pragma unroll 4
    for (int j = 0; j < TOPN; j++) rank += (sk[j] < ki) ? 1 : 0;
    unsigned idx = (unsigned)ki;
    float4 b = *(const float4*)&g_boxes[(size_t)idx * 4];
    *(float4*)&g_selbox[rank * 4] = b;
}

// ---------------- NMS ----------------
// Upper triangle only; IEEE fp32 divide (reference-exact).
__global__ void mask_kernel() {
    __shared__ float4 cb[64];
    __shared__ float ca[64];
    int jb = blockIdx.x, ib = blockIdx.y;
    if (jb < ib) return;
    int t = threadIdx.x;
    int j0 = jb * 64;
    int nj = TOPN - j0;
    if (nj > 64) nj = 64;
    if (t < nj) {
        float4 q = *(const float4*)&g_selbox[(j0 + t) * 4];
        cb[t] = q;
        ca[t] = __fmul_rn(__fadd_rn(__fsub_rn(q.z, q.x), 1.f),
                          __fadd_rn(__fsub_rn(q.w, q.y), 1.f));
    }
    __syncthreads();
    int i = ib * 64 + t;
    if (i >= TOPN) return;
    float4 rb = *(const float4*)&g_selbox[i * 4];
    float ra = __fmul_rn(__fadd_rn(__fsub_rn(rb.z, rb.x), 1.f),
                         __fadd_rn(__fsub_rn(rb.w, rb.y), 1.f));
    ull bits = 0;
    for (int c = 0; c < nj; c++) {
        float4 q = cb[c];
        float xx1 = fmaxf(rb.x, q.x), yy1 = fmaxf(rb.y, q.y);
        float xx2 = fminf(rb.z, q.z), yy2 = fminf(rb.w, q.w);
        float w = fmaxf(__fadd_rn(__fsub_rn(xx2, xx1), 1.f), 0.f);
        float h = fmaxf(__fadd_rn(__fsub_rn(yy2, yy1), 1.f), 0.f);
        float inter = __fmul_rn(w, h);
        float uni = __fsub_rn(__fadd_rn(ra, ca[c]), inter);
        float iou = __fdiv_rn(inter, uni);
        if (iou > 0.7f) bits |= (1ull << c);
    }
    g_mask[(size_t)i * NW + jb] = bits;
}

// Warp-synchronous resolution: warp 0 keeps the 94-word suppression vector in
// registers (3 ull/lane) and resolves rows barrier-free (shfl broadcast + ffs);
// warps 1-3 prefetch the next 64-row mask chunk via cp.async. One barrier pair
// per chunk (94), not per row (~3000). Visit order identical to sequential NMS.
__global__ void nms_kernel(float* __restrict__ out) {
    extern __shared__ ull buf[];          // [2][64][NW]
    __shared__ int s_kept;
    const int t = threadIdx.x;            // 128 threads
    const int lane = t & 31;
    const int warp = t >> 5;
    if (t == 0) s_kept = 0;

    const int NCHUNK = (TOPN + 63) / 64;  // 94

    auto load_chunk = [&](int c, int b) {
        int c0 = c & ~1;                  // 16B alignment
        int pairs = (NW - c0) >> 1;
        int nrows = TOPN - c * 64; if (nrows > 64) nrows = 64;
        int tot = nrows * pairs;
        int pt = t - 32;                  // 0..95 across warps 1-3
        for (int u = pt; u < tot; u += 96) {
            int il = u / pairs, pj = u - il * pairs;
            int w = c0 + pj * 2;
            CP_ASYNC16(smem_u32(&buf[((size_t)b * 64 + il) * NW + w]),
                       &g_mask[(size_t)(c * 64 + il) * NW + w]);
        }
        CP_COMMIT();
    };

    if (warp > 0) { load_chunk(0, 0); CP_WAIT0(); }
    __syncthreads();

    ull rem0 = 0, rem1 = 0, rem2 = 0;     // warp0: words lane, lane+32, lane+64
    int kept = 0;

    for (int c = 0; c < NCHUNK; c++) {
        int b = c & 1;
        if (warp > 0) {
            if (c + 1 < NCHUNK) { load_chunk(c + 1, b ^ 1); CP_WAIT0(); }
        } else {
            int nrows = TOPN - c * 64; if (nrows > 64) nrows = 64;
            ull rowmask = (nrows == 64) ? ~0ull : ((1ull << nrows) - 1ull);
            const int slot = c >> 5, owner = c & 31;
            for (;;) {
                ull myword = (slot == 0) ? rem0 : (slot == 1) ? rem1 : rem2;
                ull w = ~__shfl_sync(0xFFFFFFFFu, myword, owner) & rowmask;
                if (!w) break;
                int il = __ffsll(w) - 1;
                rowmask = (il == 63) ? 0ull : (rowmask & (~0ull << (il + 1)));
                const ull* row = &buf[((size_t)b * 64 + il) * NW];
                rem0 |= row[lane];
                if (lane + 32 < NW) rem1 |= row[lane + 32];
                if (lane + 64 < NW) rem2 |= row[lane + 64];
                if (lane == 0) {
                    int i = c * 64 + il;
                    float4 bx = *(const float4*)&g_selbox[i * 4];
                    out[kept * 5 + 0] = 0.f;
                    out[kept * 5 + 1] = bx.x;
                    out[kept * 5 + 2] = bx.y;
                    out[kept * 5 + 3] = bx.z;
                    out[kept * 5 + 4] = bx.w;
                }
                kept++;
                if (kept >= POSTN) break;
            }
            if (lane == 0) s_kept = kept;
        }
        __syncthreads();
        if (s_kept >= POSTN) break;
    }
}

// ---------------- launch ----------------
extern "C" void kernel_launch(void* const* d_in, const int* in_sizes, int n_in,
                              void* d_out, int out_size) {
    const float* features = (const float*)d_in[0];
    const float* rpn_w = (const float*)d_in[1];
    const float* rpn_b = (const float*)d_in[2];
    const float* cls_w = (const float*)d_in[3];
    const float* cls_b = (const float*)d_in[4];
    const float* box_w = (const float*)d_in[5];
    const float* box_b = (const float*)d_in[6];
    const int* imh = (const int*)d_in[7];
    const int* imw = (const int*)d_in[8];
    float* out = (float*)d_out;

    const int NMS_SMEM = 2 * 64 * NW * sizeof(ull);   // 96 KB

    static int smem_set = 0;
    if (!smem_set) {
        cudaFuncSetAttribute(nms_kernel, cudaFuncAttributeMaxDynamicSharedMemorySize, NMS_SMEM);
        smem_set = 1;
    }

    zero_kernel<<<256, 256>>>(out);
    wtrans_kernel<<<(KK * COUT + 255) / 256, 256>>>(rpn_w);
    htrans_kernel<<<54, 256>>>(cls_w, box_w);
    conv3x3_kernel<<<dim3(128, 4), 128>>>(features, rpn_b);
    head_kernel<<<128, 128>>>(cls_b, box_b, imh, imw);
    hist1_kernel<<<576, 256>>>();
    findT_kernel<<<1, 1024>>>();
    hist2_kernel<<<576, 256>>>();
    findL_kernel<<<1, 1024>>>();
    compact_kernel<<<576, 256>>>();
    eqsel_kernel<<<1, 1024>>>();
    rank_kernel<<<47, 128>>>();
    mask_kernel<<<dim3(NW, NW), 64>>>();
    nms_kernel<<<1, 128, NMS_SMEM>>>(out);
}